// round 9
// baseline (speedup 1.0000x reference)
#include <cuda_runtime.h>
#include <cuda_fp16.h>
#include <cstdint>

#define OUTF 2048
#define INF  2048
#define SWARM 32
#define MROWS (4*4096)

// Device-global scratch (no runtime allocation allowed).  int8_t everywhere:
// plain char is UNSIGNED on this aarch64 toolchain (R8 failure root cause).
__device__ int8_t g_Wb[(size_t)OUTF * INF];    // 4 MB: sign weights +/-1
__device__ int8_t g_Xh[(size_t)MROWS * INF];   // 32 MB: hi plane  rint(16x)
__device__ int8_t g_Xl[(size_t)MROWS * INF];   // 32 MB: lo plane  rint(256*(16x-h))

// ---------------------------------------------------------------------------
// Kernel 1: swarm reduction. 2 threads/row, 4 float4 each (MLP=4, coalesced).
// ---------------------------------------------------------------------------
__global__ void pop_reduce_kernel(const float* __restrict__ pop) {
    int gt  = blockIdx.x * blockDim.x + threadIdx.x;
    int row = gt >> 1;
    int c   = gt & 1;
    const float4* p = reinterpret_cast<const float4*>(pop) + ((size_t)row << 3) + (c << 2);
    float4 a = p[0], b = p[1], d = p[2], e = p[3];
    float s = (((a.x + a.y) + (a.z + a.w)) + ((b.x + b.y) + (b.z + b.w)))
            + (((d.x + d.y) + (d.z + d.w)) + ((e.x + e.y) + (e.z + e.w)));
    s += __shfl_xor_sync(0xFFFFFFFFu, s, 1);
    if (c == 0) g_Wb[row] = (s >= 0.f) ? (int8_t)1 : (int8_t)(-1);
}

// ---------------------------------------------------------------------------
// Kernel 2: x fp32 -> two int8 planes.  x ~= h/16 + l/4096, |err| <= 2^-13.
// ---------------------------------------------------------------------------
__device__ __forceinline__ void quant2(float x, int& h, int& l) {
    float x16 = x * 16.f;
    h = __float2int_rn(x16);
    h = max(-127, min(127, h));
    l = __float2int_rn((x16 - (float)h) * 256.f);
    l = max(-127, min(127, l));
}

__global__ void conv_x_kernel(const float* __restrict__ x) {
    int idx = blockIdx.x * blockDim.x + threadIdx.x;   // one float4 per thread
    float4 v = reinterpret_cast<const float4*>(x)[idx];
    int h0, l0, h1, l1, h2, l2, h3, l3;
    quant2(v.x, h0, l0); quant2(v.y, h1, l1);
    quant2(v.z, h2, l2); quant2(v.w, h3, l3);
    uint32_t hw = (uint32_t)(uint8_t)(int8_t)h0        |
                  ((uint32_t)(uint8_t)(int8_t)h1 << 8) |
                  ((uint32_t)(uint8_t)(int8_t)h2 << 16)|
                  ((uint32_t)(uint8_t)(int8_t)h3 << 24);
    uint32_t lw = (uint32_t)(uint8_t)(int8_t)l0        |
                  ((uint32_t)(uint8_t)(int8_t)l1 << 8) |
                  ((uint32_t)(uint8_t)(int8_t)l2 << 16)|
                  ((uint32_t)(uint8_t)(int8_t)l3 << 24);
    reinterpret_cast<uint32_t*>(g_Xh)[idx] = hw;
    reinterpret_cast<uint32_t*>(g_Xl)[idx] = lw;
}

// ---------------------------------------------------------------------------
// Kernel 3: dual-plane int8 GEMM, exact int32 accumulation.
// C = (Xh*W^T)/16 + (Xl*W^T)/4096, via mma.sync.m16n8k32.s8.s8.s32.
// CTA tile 128x128, K-chunk 64 bytes; 3-stage cp.async pipeline.
// ---------------------------------------------------------------------------
#define BM 128
#define BN 128
#define KB 64                 // K elements (bytes) per chunk
#define PLANE 8192            // 128 rows x 64 B
#define STAGE (3*PLANE)       // Ah + Al + B = 24 KB
#define NSTAGE 3
#define SMEM_TOTAL (NSTAGE*STAGE)

__device__ __forceinline__ uint32_t smem_u32(const void* p) {
    uint32_t a;
    asm("{ .reg .u64 t; cvta.to.shared.u64 t, %1; cvt.u32.u64 %0, t; }"
        : "=r"(a) : "l"(p));
    return a;
}

__device__ __forceinline__ void ldsm_x4(uint32_t* r, uint32_t addr) {
    asm volatile("ldmatrix.sync.aligned.m8n8.x4.shared.b16 {%0,%1,%2,%3}, [%4];"
                 : "=r"(r[0]), "=r"(r[1]), "=r"(r[2]), "=r"(r[3]) : "r"(addr));
}

__device__ __forceinline__ void imma(int32_t* d, const uint32_t* a,
                                     uint32_t b0, uint32_t b1) {
    asm volatile(
        "mma.sync.aligned.m16n8k32.row.col.s32.s8.s8.s32 "
        "{%0,%1,%2,%3}, {%4,%5,%6,%7}, {%8,%9}, {%0,%1,%2,%3};"
        : "+r"(d[0]), "+r"(d[1]), "+r"(d[2]), "+r"(d[3])
        : "r"(a[0]), "r"(a[1]), "r"(a[2]), "r"(a[3]), "r"(b0), "r"(b1));
}

#define SWZ(row, ch) (((row) * 64) + ((((ch) ^ (((row) >> 1) & 3))) << 4))

__global__ __launch_bounds__(256, 2)
void gemm_imma_kernel(float* __restrict__ C) {
    extern __shared__ __align__(1024) char smem[];
    const uint32_t sbase = smem_u32(smem);

    const int tid  = threadIdx.x;
    const int warp = tid >> 5;
    const int lane = tid & 31;
    const int warpM = warp & 3;       // 32-row slab
    const int warpN = warp >> 2;      // 64-col slab
    const int g   = lane >> 2;
    const int tig = lane & 3;
    const int r8  = lane & 7;
    const int mh  = (lane >> 3) & 1;
    const int mk  = lane >> 4;

    const int blockM = blockIdx.y * BM;   // grid.x = N (fastest): L2 reuse of A
    const int blockN = blockIdx.x * BN;

    int32_t acch[2][8][4], accl[2][8][4];
#pragma unroll
    for (int mi = 0; mi < 2; mi++)
#pragma unroll
        for (int ni = 0; ni < 8; ni++)
#pragma unroll
            for (int r = 0; r < 4; r++) { acch[mi][ni][r] = 0; accl[mi][ni][r] = 0; }

    // fill chunk c into stage c%3: 2x (Ah,Al,B) 16B cp.async per thread
    auto fill = [&](int c) {
        const uint32_t ab = sbase + (c % NSTAGE) * STAGE;
        const int k0 = c * KB;
#pragma unroll
        for (int t = 0; t < 2; t++) {
            int id  = t * 256 + tid;          // 0..511
            int row = id >> 2, ch = id & 3;
            uint32_t off = SWZ(row, ch);
            const void* sh = g_Xh + (size_t)(blockM + row) * INF + k0 + ch * 16;
            asm volatile("cp.async.cg.shared.global [%0], [%1], 16;" :: "r"(ab + off), "l"(sh));
            const void* sl = g_Xl + (size_t)(blockM + row) * INF + k0 + ch * 16;
            asm volatile("cp.async.cg.shared.global [%0], [%1], 16;" :: "r"(ab + PLANE + off), "l"(sl));
            const void* sb = g_Wb + (size_t)(blockN + row) * INF + k0 + ch * 16;
            asm volatile("cp.async.cg.shared.global [%0], [%1], 16;" :: "r"(ab + 2 * PLANE + off), "l"(sb));
        }
        asm volatile("cp.async.commit_group;");
    };

    const int KT = INF / KB;   // 32 chunks
    fill(0);
    fill(1);

    for (int c = 0; c < KT; c++) {
        if (c + 1 < KT) asm volatile("cp.async.wait_group 1;");
        else            asm volatile("cp.async.wait_group 0;");
        __syncthreads();
        if (c + 2 < KT) fill(c + 2);

        const uint32_t ab = sbase + (c % NSTAGE) * STAGE;

#pragma unroll
        for (int ks = 0; ks < 2; ks++) {
            uint32_t ah[2][4], al[2][4], b[4][4];
            const int cha = ks * 2 + mk;
            const int chb = ks * 2 + mh;
#pragma unroll
            for (int mi = 0; mi < 2; mi++) {
                int row = warpM * 32 + mi * 16 + mh * 8 + r8;
                uint32_t off = SWZ(row, cha);
                ldsm_x4(ah[mi], ab + off);
                ldsm_x4(al[mi], ab + PLANE + off);
            }
#pragma unroll
            for (int p = 0; p < 4; p++) {
                int row = warpN * 64 + p * 16 + mk * 8 + r8;
                ldsm_x4(b[p], ab + 2 * PLANE + SWZ(row, chb));
            }
#pragma unroll
            for (int mi = 0; mi < 2; mi++)
#pragma unroll
                for (int ni = 0; ni < 8; ni++) {
                    const uint32_t b0 = b[ni >> 1][(ni & 1) * 2];
                    const uint32_t b1 = b[ni >> 1][(ni & 1) * 2 + 1];
                    imma(acch[mi][ni], ah[mi], b0, b1);
                    imma(accl[mi][ni], al[mi], b0, b1);
                }
        }
    }

    // epilogue: C = acch/16 + accl/4096  (exact int32 -> fp32)
    const float SH = 1.f / 16.f, SL = 1.f / 4096.f;
#pragma unroll
    for (int mi = 0; mi < 2; mi++) {
        int row0 = blockM + warpM * 32 + mi * 16 + g;
#pragma unroll
        for (int ni = 0; ni < 8; ni++) {
            int col = blockN + warpN * 64 + ni * 8 + tig * 2;
            float2 v0, v1;
            v0.x = fmaf((float)accl[mi][ni][0], SL, (float)acch[mi][ni][0] * SH);
            v0.y = fmaf((float)accl[mi][ni][1], SL, (float)acch[mi][ni][1] * SH);
            v1.x = fmaf((float)accl[mi][ni][2], SL, (float)acch[mi][ni][2] * SH);
            v1.y = fmaf((float)accl[mi][ni][3], SL, (float)acch[mi][ni][3] * SH);
            *reinterpret_cast<float2*>(C + (size_t)row0 * OUTF + col)       = v0;
            *reinterpret_cast<float2*>(C + (size_t)(row0 + 8) * OUTF + col) = v1;
        }
    }
}

// ---------------------------------------------------------------------------
extern "C" void kernel_launch(void* const* d_in, const int* in_sizes, int n_in,
                              void* d_out, int out_size) {
    const float* x   = (const float*)d_in[0];
    const float* pop = (const float*)d_in[1];
    if (n_in >= 2 && in_sizes[0] == OUTF * INF * SWARM) {
        pop = (const float*)d_in[0];
        x   = (const float*)d_in[1];
    }
    float* out = (float*)d_out;

    // not a stream op; deterministic every call; safe under graph capture
    cudaFuncSetAttribute(gemm_imma_kernel,
                         cudaFuncAttributeMaxDynamicSharedMemorySize, SMEM_TOTAL);

    {
        int nthreads = OUTF * INF * 2;   // 2 threads per swarm row
        pop_reduce_kernel<<<nthreads / 256, 256>>>(pop);
    }
    {
        int n4 = (MROWS * INF) / 4;
        conv_x_kernel<<<n4 / 256, 256>>>(x);
    }
    {
        dim3 grid(OUTF / BN, MROWS / BM);   // x = N-blocks (fastest), y = M-blocks
        gemm_imma_kernel<<<grid, 256, SMEM_TOTAL>>>(out);
    }
}

// round 12
// speedup vs baseline: 3.4070x; 3.4070x over previous
#include <cuda_runtime.h>
#include <cuda_fp16.h>
#include <cstdint>

#define OUTF 2048
#define INF  2048
#define SWARM 32
#define MROWS (4*4096)

// Device-global scratch (no runtime allocation allowed)
__device__ __half g_W[(size_t)OUTF * INF];   // 8 MB: sign weights, +/-1 in fp16
__device__ __half g_X[(size_t)MROWS * INF];  // 64 MB: x converted to fp16

// ---------------------------------------------------------------------------
// Kernel 1: swarm reduction.
// 8 threads per row (perfect coalescing: each warp-wide LDG.128 covers exactly
// four full 128B lines) x 4 rows per thread (MLP=4 independent loads).
// ---------------------------------------------------------------------------
__global__ void pop_reduce_kernel(const float* __restrict__ pop) {
    int gt      = blockIdx.x * blockDim.x + threadIdx.x;
    int c       = gt & 7;            // chunk within row (float4 granule)
    int rowbase = (gt >> 3) * 4;     // this thread covers rows rowbase..rowbase+3
    const float4* p = reinterpret_cast<const float4*>(pop);

    float4 v0 = p[((size_t)(rowbase + 0) << 3) + c];
    float4 v1 = p[((size_t)(rowbase + 1) << 3) + c];
    float4 v2 = p[((size_t)(rowbase + 2) << 3) + c];
    float4 v3 = p[((size_t)(rowbase + 3) << 3) + c];

    float s0 = (v0.x + v0.y) + (v0.z + v0.w);
    float s1 = (v1.x + v1.y) + (v1.z + v1.w);
    float s2 = (v2.x + v2.y) + (v2.z + v2.w);
    float s3 = (v3.x + v3.y) + (v3.z + v3.w);
#pragma unroll
    for (int d = 1; d <= 4; d <<= 1) {
        s0 += __shfl_xor_sync(0xFFFFFFFFu, s0, d);
        s1 += __shfl_xor_sync(0xFFFFFFFFu, s1, d);
        s2 += __shfl_xor_sync(0xFFFFFFFFu, s2, d);
        s3 += __shfl_xor_sync(0xFFFFFFFFu, s3, d);
    }
    if (c == 0) {
        g_W[rowbase + 0] = __float2half(s0 >= 0.f ? 1.f : -1.f);
        g_W[rowbase + 1] = __float2half(s1 >= 0.f ? 1.f : -1.f);
        g_W[rowbase + 2] = __float2half(s2 >= 0.f ? 1.f : -1.f);
        g_W[rowbase + 3] = __float2half(s3 >= 0.f ? 1.f : -1.f);
    }
}

// ---------------------------------------------------------------------------
// Kernel 2: x fp32 -> fp16 (2 float4 per thread for MLP)
// ---------------------------------------------------------------------------
__global__ void conv_x_kernel(const float* __restrict__ x) {
    int idx = (blockIdx.x * blockDim.x + threadIdx.x) * 2;
    float4 v0 = reinterpret_cast<const float4*>(x)[idx];
    float4 v1 = reinterpret_cast<const float4*>(x)[idx + 1];
    __half2* o = reinterpret_cast<__half2*>(g_X + (size_t)idx * 4);
    o[0] = __floats2half2_rn(v0.x, v0.y);
    o[1] = __floats2half2_rn(v0.z, v0.w);
    o[2] = __floats2half2_rn(v1.x, v1.y);
    o[3] = __floats2half2_rn(v1.z, v1.w);
}

// ---------------------------------------------------------------------------
// Kernel 3: GEMM  C[M,N] = X[M,K] * W^T   (W is [N,K], K contiguous for both)
// mma.sync.m16n8k16 + ldmatrix.x4 fragment loads + 3-stage cp.async pipeline.
// CTA tile 128x128x32, 8 warps 4(M) x 2(N), warp tile 32x64.
// Measured at the legacy-HMMA pipe cap (~288 TF/s) — this is the ISA floor.
// ---------------------------------------------------------------------------
#define BM 128
#define BN 128
#define BK 32
#define STAGE 16384        // A 8KB + B 8KB
#define NSTAGE 3

__device__ __forceinline__ uint32_t smem_u32(const void* p) {
    uint32_t a;
    asm("{ .reg .u64 t; cvta.to.shared.u64 t, %1; cvt.u32.u64 %0, t; }"
        : "=r"(a) : "l"(p));
    return a;
}

__device__ __forceinline__ void ldsm_x4(uint32_t* r, uint32_t addr) {
    asm volatile("ldmatrix.sync.aligned.m8n8.x4.shared.b16 {%0,%1,%2,%3}, [%4];"
                 : "=r"(r[0]), "=r"(r[1]), "=r"(r[2]), "=r"(r[3]) : "r"(addr));
}

__global__ __launch_bounds__(256, 2)
void gemm_hmma_kernel(float* __restrict__ C) {
    __shared__ __align__(1024) char smem[NSTAGE * STAGE];
    const uint32_t sbase = smem_u32(smem);

    const int tid  = threadIdx.x;
    const int warp = tid >> 5;
    const int lane = tid & 31;
    const int warpM = warp & 3;       // 0..3 -> 32-row slab
    const int warpN = warp >> 2;      // 0..1 -> 64-col slab
    const int g   = lane >> 2;        // group id 0..7 (epilogue)
    const int tig = lane & 3;

    // ldmatrix lane decomposition
    const int r8  = lane & 7;
    const int mh  = (lane >> 3) & 1;  // matrix-pair select bit
    const int mk  = lane >> 4;        // 0/1

    const int blockM = blockIdx.y * BM;   // grid.x = N-blocks (fastest): L2 A reuse
    const int blockN = blockIdx.x * BN;

    float acc[2][8][4];
#pragma unroll
    for (int mi = 0; mi < 2; mi++)
#pragma unroll
        for (int ni = 0; ni < 8; ni++)
#pragma unroll
            for (int r = 0; r < 4; r++) acc[mi][ni][r] = 0.f;

    // async fill of tile c into stage c%3: per thread 2 A-chunks + 2 B-chunks (16B)
    auto fill = [&](int c) {
        const int s = c % NSTAGE;
        const uint32_t ab = sbase + s * STAGE;
        const uint32_t bb = ab + 8192;
        const int k0 = c * BK;
#pragma unroll
        for (int t = 0; t < 2; t++) {
            int id  = t * 256 + tid;          // 0..511
            int row = id >> 2, ch = id & 3;
            uint32_t da = ab + row * 64 + ((ch ^ (row & 3)) << 4);
            const void* sa = g_X + (size_t)(blockM + row) * INF + k0 + ch * 8;
            asm volatile("cp.async.cg.shared.global [%0], [%1], 16;" :: "r"(da), "l"(sa));
            uint32_t db = bb + row * 64 + ((ch ^ (row & 3)) << 4);
            const void* sb = g_W + (size_t)(blockN + row) * INF + k0 + ch * 8;
            asm volatile("cp.async.cg.shared.global [%0], [%1], 16;" :: "r"(db), "l"(sb));
        }
        asm volatile("cp.async.commit_group;");
    };

    const int KT = INF / BK;   // 64 tiles
    fill(0);
    fill(1);

    for (int c = 0; c < KT; c++) {
        if (c + 1 < KT) asm volatile("cp.async.wait_group 1;");
        else            asm volatile("cp.async.wait_group 0;");
        __syncthreads();
        if (c + 2 < KT) fill(c + 2);

        const uint32_t ab = sbase + (c % NSTAGE) * STAGE;
        const uint32_t bb = ab + 8192;

#pragma unroll
        for (int ks = 0; ks < 2; ks++) {
            uint32_t a[2][4], b[4][4];
#pragma unroll
            for (int mi = 0; mi < 2; mi++) {
                int row = warpM * 32 + mi * 16 + mh * 8 + r8;
                int ch  = ks * 2 + mk;
                ldsm_x4(a[mi], ab + row * 64 + ((ch ^ (row & 3)) << 4));
            }
#pragma unroll
            for (int p = 0; p < 4; p++) {
                int row = warpN * 64 + p * 16 + mk * 8 + r8;
                int ch  = ks * 2 + mh;
                ldsm_x4(b[p], bb + row * 64 + ((ch ^ (row & 3)) << 4));
            }
#pragma unroll
            for (int mi = 0; mi < 2; mi++)
#pragma unroll
                for (int ni = 0; ni < 8; ni++) {
                    const uint32_t b0 = b[ni >> 1][(ni & 1) * 2];
                    const uint32_t b1 = b[ni >> 1][(ni & 1) * 2 + 1];
                    asm volatile(
                        "mma.sync.aligned.m16n8k16.row.col.f32.f16.f16.f32 "
                        "{%0,%1,%2,%3}, {%4,%5,%6,%7}, {%8,%9}, {%0,%1,%2,%3};"
                        : "+f"(acc[mi][ni][0]), "+f"(acc[mi][ni][1]),
                          "+f"(acc[mi][ni][2]), "+f"(acc[mi][ni][3])
                        : "r"(a[mi][0]), "r"(a[mi][1]), "r"(a[mi][2]), "r"(a[mi][3]),
                          "r"(b0), "r"(b1));
                }
        }
    }

    // epilogue
#pragma unroll
    for (int mi = 0; mi < 2; mi++) {
        int row0 = blockM + warpM * 32 + mi * 16 + g;
#pragma unroll
        for (int ni = 0; ni < 8; ni++) {
            int col = blockN + warpN * 64 + ni * 8 + tig * 2;
            float2 v0 = make_float2(acc[mi][ni][0], acc[mi][ni][1]);
            float2 v1 = make_float2(acc[mi][ni][2], acc[mi][ni][3]);
            *reinterpret_cast<float2*>(C + (size_t)row0 * OUTF + col)       = v0;
            *reinterpret_cast<float2*>(C + (size_t)(row0 + 8) * OUTF + col) = v1;
        }
    }
}

// ---------------------------------------------------------------------------
extern "C" void kernel_launch(void* const* d_in, const int* in_sizes, int n_in,
                              void* d_out, int out_size) {
    const float* x   = (const float*)d_in[0];
    const float* pop = (const float*)d_in[1];
    if (n_in >= 2 && in_sizes[0] == OUTF * INF * SWARM) {
        pop = (const float*)d_in[0];
        x   = (const float*)d_in[1];
    }
    float* out = (float*)d_out;

    {
        int nthreads = OUTF * INF * 2;   // 8 thr/row, 4 rows/thread
        pop_reduce_kernel<<<nthreads / 256, 256>>>(pop);
    }
    {
        int nthreads = (MROWS * INF) / 8;   // 2 float4 per thread
        conv_x_kernel<<<nthreads / 256, 256>>>(x);
    }
    {
        dim3 grid(OUTF / BN, MROWS / BM);   // x = N-blocks (fastest), y = M-blocks
        gemm_hmma_kernel<<<grid, 256>>>(out);
    }
}